// round 15
// baseline (speedup 1.0000x reference)
#include <cuda_runtime.h>
#include <cstdint>

#define BB 8
#define CC 512
#define DD 64
#define NN 16384
#define PARAM 10.0f
#define EPS 1e-6f

__device__ float g_Q[BB*DD*NN];     // phi(Q) [b][m][n]
__device__ float g_Kt[BB*NN*DD];    // phi(K) transposed [b][n][m]
__device__ float g_Ksum[BB*DD];
__device__ float g_KXT[BB*CC*DD];   // (phiK @ x^T)^T [b][c][m]
__device__ float g_KVT[BB*CC*DD];   // KV^T (no bias) [b][c][m]

__device__ __forceinline__ float fmap(float t) {
    return t > 0.f ? fmaf(PARAM, t, 1.f) : __expf(PARAM * t);
}
__device__ __forceinline__ uint32_t smaddr(const void* p) {
    return (uint32_t)__cvta_generic_to_shared(p);
}
#define CPA(d, s) asm volatile("cp.async.cg.shared.global [%0], [%1], 16;" \
        :: "r"(d), "l"(s) : "memory")
#define CPC()  asm volatile("cp.async.commit_group;" ::: "memory")
#define CPW0() asm volatile("cp.async.wait_group 0;" ::: "memory")
#define CPW1() asm volatile("cp.async.wait_group 1;" ::: "memory")
#define CPW2() asm volatile("cp.async.wait_group 2;" ::: "memory")
#define MMA8(d, a, b0, b1) \
    asm volatile("mma.sync.aligned.m16n8k8.row.col.f32.tf32.tf32.f32 " \
        "{%0,%1,%2,%3}, {%4,%5,%6,%7}, {%8,%9}, {%0,%1,%2,%3};" \
        : "+f"((d)[0]), "+f"((d)[1]), "+f"((d)[2]), "+f"((d)[3]) \
        : "r"((a)[0]), "r"((a)[1]), "r"((a)[2]), "r"((a)[3]), "r"(b0), "r"(b1))

// ---------------------------------------------------------------------------
__global__ void k_zeroA() {
    int i = threadIdx.x;
    if (i < BB*DD) g_Ksum[i] = 0.f;
}
__global__ void k_zeroB() {
    int i = blockIdx.x*blockDim.x + threadIdx.x;
    if (i < BB*CC*DD) { g_KXT[i] = 0.f; g_KVT[i] = 0.f; }
}

// ---------------------------------------------------------------------------
// k_qk: [Wq;Wk](128x512) @ x_tile(512 x 128n). cp.async 2-stage, 2 blocks/SM.
// Epilogue: bias+fmap; Q->g_Q, K->g_Kt + Ksum atomics.
// ---------------------------------------------------------------------------
__global__ __launch_bounds__(256, 2) void k_qk(const float* __restrict__ x,
        const float* __restrict__ Wq, const float* __restrict__ bq,
        const float* __restrict__ Wk, const float* __restrict__ bk) {
    extern __shared__ float S[];   // 2 x (As 128*36 + Bs 32*136) = 2*8960
    const int tid = threadIdx.x, w = tid>>5, lane = tid&31;
    const int gr = lane>>2, qt = lane&3;
    const int b = blockIdx.y, n0 = blockIdx.x*128;
    const int M0 = (w>>1)*32, N0 = (w&1)*64;
    const float* xb = x + (size_t)b*CC*NN;

    auto issue = [&](int st, int kc) {
        float* As = S + st*8960;
        float* Bs = As + 4608;
        #pragma unroll
        for (int i = 0; i < 4; i++) {
            int id = tid + i*256, r = id>>3, c4 = id&7;
            const float* src = (r < 64 ? Wq + r*CC : Wk + (size_t)(r-64)*CC)
                               + kc + c4*4;
            CPA(smaddr(&As[r*36 + c4*4]), src);
        }
        #pragma unroll
        for (int i = 0; i < 4; i++) {
            int id = tid + i*256, r = id>>5, n4 = id&31;
            CPA(smaddr(&Bs[r*136 + n4*4]), xb + (size_t)(kc+r)*NN + n0 + n4*4);
        }
        CPC();
    };

    float acc[2][8][4];
    #pragma unroll
    for (int mt = 0; mt < 2; mt++)
        #pragma unroll
        for (int nt = 0; nt < 8; nt++)
            #pragma unroll
            for (int i = 0; i < 4; i++) acc[mt][nt][i] = 0.f;

    issue(0, 0);
    for (int ci = 0; ci < 16; ci++) {
        CPW0();
        __syncthreads();
        if (ci < 15) issue((ci+1)&1, (ci+1)*32);
        float* As = S + (ci&1)*8960;
        float* Bs = As + 4608;
        #pragma unroll
        for (int k0 = 0; k0 < 32; k0 += 8) {
            uint32_t af[2][4], bf[8][2];
            #pragma unroll
            for (int mt = 0; mt < 2; mt++) {
                int base = (M0 + 16*mt + gr)*36 + k0 + qt;
                af[mt][0] = __float_as_uint(As[base]);
                af[mt][1] = __float_as_uint(As[base + 8*36]);
                af[mt][2] = __float_as_uint(As[base + 4]);
                af[mt][3] = __float_as_uint(As[base + 8*36 + 4]);
            }
            #pragma unroll
            for (int nt = 0; nt < 8; nt++) {
                int bb = (k0 + qt)*136 + N0 + 8*nt + gr;
                bf[nt][0] = __float_as_uint(Bs[bb]);
                bf[nt][1] = __float_as_uint(Bs[bb + 4*136]);
            }
            #pragma unroll
            for (int mt = 0; mt < 2; mt++)
                #pragma unroll
                for (int nt = 0; nt < 8; nt++)
                    MMA8(acc[mt][nt], af[mt], bf[nt][0], bf[nt][1]);
        }
    }

    #pragma unroll
    for (int mt = 0; mt < 2; mt++)
        #pragma unroll
        for (int h = 0; h < 2; h++) {
            const int m = M0 + 16*mt + 8*h + gr;
            const float bias = m < 64 ? __ldg(bq + m) : __ldg(bk + m - 64);
            float vv[8][2], ks = 0.f;
            #pragma unroll
            for (int nt = 0; nt < 8; nt++) {
                vv[nt][0] = fmap(acc[mt][nt][2*h]   + bias);
                vv[nt][1] = fmap(acc[mt][nt][2*h+1] + bias);
                ks += vv[nt][0] + vv[nt][1];
            }
            if (m < 64) {
                float* dst = g_Q + ((size_t)b*DD + m)*NN + n0 + N0;
                #pragma unroll
                for (int nt = 0; nt < 8; nt++)
                    *(float2*)(dst + 8*nt + 2*qt) = make_float2(vv[nt][0], vv[nt][1]);
            } else {
                const int mm = m - 64;
                #pragma unroll
                for (int nt = 0; nt < 8; nt++) {
                    int n = n0 + N0 + 8*nt + 2*qt;
                    float* dk = g_Kt + ((size_t)b*NN + n)*DD + mm;
                    dk[0] = vv[nt][0]; dk[DD] = vv[nt][1];
                }
                ks += __shfl_xor_sync(0xffffffffu, ks, 1);
                ks += __shfl_xor_sync(0xffffffffu, ks, 2);
                if (qt == 0) atomicAdd(&g_Ksum[b*DD + mm], ks);
            }
        }
}

// ---------------------------------------------------------------------------
// k_kx: KXT[256c][64m] += x_tile @ phiK^T. cp.async 2-stage, 2 blocks/SM,
// warp tile 64c x 32m (mt=4), split-K=16, L2 atomics.
// ---------------------------------------------------------------------------
__global__ __launch_bounds__(256, 2) void k_kx(const float* __restrict__ x) {
    extern __shared__ float S[];   // 2 x (As 256*36=9216 + Bs 32*72=2304)
    const int tid = threadIdx.x, w = tid>>5, lane = tid&31;
    const int gr = lane>>2, qt = lane&3;
    const int c0 = blockIdx.x*256, b = blockIdx.z;
    const int nbase = blockIdx.y*(NN/16);
    const int CW = (w>>1)*64, N0 = (w&1)*32;

    auto issue = [&](int st, int kn) {
        float* As = S + st*11520;
        float* Bs = As + 9216;
        #pragma unroll
        for (int i = 0; i < 8; i++) {
            int id = tid + i*256, r = id>>3, n4 = id&7;
            CPA(smaddr(&As[r*36 + n4*4]),
                x + ((size_t)(b*CC + c0 + r))*NN + kn + n4*4);
        }
        #pragma unroll
        for (int i = 0; i < 2; i++) {
            int id = tid + i*256, r = id>>4, m4 = id&15;
            CPA(smaddr(&Bs[r*72 + m4*4]),
                g_Kt + ((size_t)b*NN + kn + r)*DD + m4*4);
        }
        CPC();
    };

    float acc[4][4][4];
    #pragma unroll
    for (int mt = 0; mt < 4; mt++)
        #pragma unroll
        for (int nt = 0; nt < 4; nt++)
            #pragma unroll
            for (int i = 0; i < 4; i++) acc[mt][nt][i] = 0.f;

    issue(0, nbase);
    for (int ci = 0; ci < 32; ci++) {
        CPW0();
        __syncthreads();
        if (ci < 31) issue((ci+1)&1, nbase + (ci+1)*32);
        float* As = S + (ci&1)*11520;
        float* Bs = As + 9216;
        #pragma unroll
        for (int k0 = 0; k0 < 32; k0 += 8) {
            uint32_t bf[4][2];
            #pragma unroll
            for (int nt = 0; nt < 4; nt++) {
                int bb = (k0 + qt)*72 + N0 + 8*nt + gr;
                bf[nt][0] = __float_as_uint(Bs[bb]);
                bf[nt][1] = __float_as_uint(Bs[bb + 4*72]);
            }
            #pragma unroll
            for (int mt = 0; mt < 4; mt++) {
                uint32_t af[4];
                int base = (CW + 16*mt + gr)*36 + k0 + qt;
                af[0] = __float_as_uint(As[base]);
                af[1] = __float_as_uint(As[base + 8*36]);
                af[2] = __float_as_uint(As[base + 4]);
                af[3] = __float_as_uint(As[base + 8*36 + 4]);
                #pragma unroll
                for (int nt = 0; nt < 4; nt++)
                    MMA8(acc[mt][nt], af, bf[nt][0], bf[nt][1]);
            }
        }
    }
    #pragma unroll
    for (int mt = 0; mt < 4; mt++)
        #pragma unroll
        for (int h = 0; h < 2; h++) {
            int c = c0 + CW + 16*mt + 8*h + gr;
            #pragma unroll
            for (int nt = 0; nt < 4; nt++) {
                int m = N0 + 8*nt + 2*qt;
                float* d = g_KXT + ((size_t)b*CC + c)*DD + m;
                atomicAdd(d,     acc[mt][nt][2*h]);
                atomicAdd(d + 1, acc[mt][nt][2*h+1]);
            }
        }
}

// ---------------------------------------------------------------------------
// k_kv (SIMT, split-K=4): KVT[c][m] += sum_{c'} Wv[c][c'] * KXT[c'][m]
// ---------------------------------------------------------------------------
__global__ __launch_bounds__(256) void k_kv(const float* __restrict__ Wv) {
    __shared__ float Ws[64*36];
    __shared__ float Xs[32*68];
    const int c0 = blockIdx.x*64, sp = blockIdx.y, b = blockIdx.z;
    const int tid = threadIdx.x, tx = tid&15, ty = tid>>4;

    float acc[4][4] = {};
    for (int kk = 0; kk < 4; kk++) {
        const int cp0 = sp*128 + kk*32;
        #pragma unroll
        for (int i = 0; i < 2; i++) {
            int id = tid + i*256, r = id>>3, q4 = id&7;
            *(float4*)&Ws[r*36 + q4*4] =
                *(const float4*)(Wv + (size_t)(c0 + r)*CC + cp0 + q4*4);
        }
        #pragma unroll
        for (int i = 0; i < 2; i++) {
            int id = tid + i*256, r = id>>4, m4 = id&15;
            *(float4*)&Xs[r*68 + m4*4] =
                *(const float4*)(g_KXT + ((size_t)(b*CC) + cp0 + r)*DD + m4*4);
        }
        __syncthreads();
        #pragma unroll
        for (int k = 0; k < 32; k++) {
            float a[4], bb[4];
            #pragma unroll
            for (int i = 0; i < 4; i++) a[i] = Ws[(ty*4+i)*36 + k];
            #pragma unroll
            for (int j = 0; j < 4; j++) bb[j] = Xs[k*68 + tx*4 + j];
            #pragma unroll
            for (int i = 0; i < 4; i++)
                #pragma unroll
                for (int j = 0; j < 4; j++)
                    acc[i][j] = fmaf(a[i], bb[j], acc[i][j]);
        }
        __syncthreads();
    }
    #pragma unroll
    for (int i = 0; i < 4; i++)
        #pragma unroll
        for (int j = 0; j < 4; j++)
            atomicAdd(&g_KVT[((size_t)b*CC + c0 + ty*4+i)*DD + tx*4 + j], acc[i][j]);
}

// ---------------------------------------------------------------------------
// k_out: one block owns a 64-n stripe. B=phiQ loaded once; A = raw KVT via
// 4-stage cp.async (bias hoisted: out += bv[c]*kq[n]); x prefetched into
// registers at chunk start. 2 blocks/SM.
// ---------------------------------------------------------------------------
__global__ __launch_bounds__(256, 2) void k_out(const float* __restrict__ x,
        const float* __restrict__ bv, const float* __restrict__ gamma,
        float* __restrict__ out) {
    extern __shared__ float S[];         // As[4][64*68]=4*4352 then Bs[64*72]
    float* Bs = S + 4*4352;
    __shared__ float rns[64], kqn[64], kss[64];
    const int tid = threadIdx.x, w = tid>>5, lane = tid&31;
    const int gr = lane>>2, qt = lane&3;
    const int n0 = blockIdx.x*64, b = blockIdx.y;
    const int M0 = (w>>1)*16, N0 = (w&1)*32;
    const float* kvb = g_KVT + (size_t)b*CC*DD;

    auto issueA = [&](int st, int c0) {
        float* As = S + st*4352;
        #pragma unroll
        for (int i = 0; i < 4; i++) {
            int id = tid + i*256, r = id>>4, m4 = id&15;
            CPA(smaddr(&As[r*68 + m4*4]), kvb + (size_t)(c0 + r)*DD + m4*4);
        }
        CPC();
    };

    issueA(0, 0);
    issueA(1, 64);
    issueA(2, 128);
    if (tid < 64) kss[tid] = g_Ksum[b*DD + tid];
    #pragma unroll
    for (int i = 0; i < 4; i++) {        // B = phiQ [m][n], loaded once
        int id = tid + i*256, r = id>>4, n4 = id&15;
        *(float4*)&Bs[r*72 + n4*4] =
            *(const float4*)(g_Q + ((size_t)b*DD + r)*NN + n0 + n4*4);
    }
    __syncthreads();
    const float gm = gamma[0];
    if (tid < 64) {                      // den, qsum -> rns, kqn
        float d = 0.f, q = 0.f;
        #pragma unroll 16
        for (int m = 0; m < 64; m++) {
            float qv = Bs[m*72 + tid];
            d = fmaf(qv, kss[m] + EPS, d);
            q += qv;
        }
        rns[tid] = gm / d;
        kqn[tid] = d - EPS*q;            // sum_m Ksum[m]*Q[m][n]
    }

    for (int cc = 0; cc < 8; cc++) {
        const int c0 = cc*64;
        if (cc <= 5) { CPW2(); } else if (cc == 6) { CPW1(); } else { CPW0(); }
        __syncthreads();                 // As(cc) ready; rns/kqn visible
        if (cc < 5) issueA((cc+3)&3, c0 + 192);
        float* As = S + (cc&3)*4352;

        // prefetch residual x for this chunk (used in epilogue)
        float2 xv[2][4];
        #pragma unroll
        for (int h = 0; h < 2; h++) {
            const int c = c0 + M0 + 8*h + gr;
            #pragma unroll
            for (int nt = 0; nt < 4; nt++)
                xv[h][nt] = *(const float2*)(x +
                    ((size_t)b*CC + c)*NN + n0 + N0 + 8*nt + 2*qt);
        }

        float acc[4][4];
        #pragma unroll
        for (int nt = 0; nt < 4; nt++)
            #pragma unroll
            for (int i = 0; i < 4; i++) acc[nt][i] = 0.f;
        #pragma unroll
        for (int k0 = 0; k0 < 64; k0 += 8) {
            uint32_t af[4], bf[4][2];
            int base = (M0 + gr)*68 + k0 + qt;
            af[0] = __float_as_uint(As[base]);
            af[1] = __float_as_uint(As[base + 8*68]);
            af[2] = __float_as_uint(As[base + 4]);
            af[3] = __float_as_uint(As[base + 8*68 + 4]);
            #pragma unroll
            for (int nt = 0; nt < 4; nt++) {
                int bb = (k0 + qt)*72 + N0 + 8*nt + gr;
                bf[nt][0] = __float_as_uint(Bs[bb]);
                bf[nt][1] = __float_as_uint(Bs[bb + 4*72]);
            }
            #pragma unroll
            for (int nt = 0; nt < 4; nt++)
                MMA8(acc[nt], af, bf[nt][0], bf[nt][1]);
        }
        #pragma unroll
        for (int h = 0; h < 2; h++) {
            const int c = c0 + M0 + 8*h + gr;
            const float bvc = __ldg(bv + c);
            #pragma unroll
            for (int nt = 0; nt < 4; nt++) {
                const int nl = N0 + 8*nt + 2*qt;
                const size_t bi = ((size_t)b*CC + c)*NN + n0 + nl;
                float t0 = fmaf(bvc, kqn[nl],   acc[nt][2*h]);
                float t1 = fmaf(bvc, kqn[nl+1], acc[nt][2*h+1]);
                float2 o;
                o.x = fmaf(t0, rns[nl],   xv[h][nt].x);
                o.y = fmaf(t1, rns[nl+1], xv[h][nt].y);
                *(float2*)(out + bi) = o;
            }
        }
    }
}

// ---------------------------------------------------------------------------
extern "C" void kernel_launch(void* const* d_in, const int* in_sizes, int n_in,
                              void* d_out, int out_size) {
    const float* x     = (const float*)d_in[0];
    const float* Wq    = (const float*)d_in[1];
    const float* bq    = (const float*)d_in[2];
    const float* Wk    = (const float*)d_in[3];
    const float* bk    = (const float*)d_in[4];
    const float* Wv    = (const float*)d_in[5];
    const float* bv    = (const float*)d_in[6];
    const float* gamma = (const float*)d_in[7];
    float* out = (float*)d_out;

    cudaFuncSetAttribute(k_qk,  cudaFuncAttributeMaxDynamicSharedMemorySize, 71680);
    cudaFuncSetAttribute(k_kx,  cudaFuncAttributeMaxDynamicSharedMemorySize, 92160);
    cudaFuncSetAttribute(k_out, cudaFuncAttributeMaxDynamicSharedMemorySize, 88064);

    k_zeroA<<<1, 512>>>();
    k_zeroB<<<512, 512>>>();
    k_qk  <<<dim3(NN/128, BB), 256, 71680>>>(x, Wq, bq, Wk, bk);
    k_kx  <<<dim3(CC/256, 16, BB), 256, 92160>>>(x);
    k_kv  <<<dim3(CC/64, 4, BB), 256>>>(Wv);
    k_out <<<dim3(NN/64, BB), 256, 88064>>>(x, bv, gamma, out);
}

// round 16
// speedup vs baseline: 1.0666x; 1.0666x over previous
#include <cuda_runtime.h>
#include <cstdint>

#define BB 8
#define CC 512
#define DD 64
#define NN 16384
#define PARAM 10.0f
#define EPS 1e-6f

__device__ float g_Q[BB*DD*NN];     // phi(Q) [b][m][n]
__device__ float g_Kt[BB*NN*DD];    // phi(K) transposed [b][n][m]
__device__ float g_Ksum[BB*DD];
__device__ float g_KXT[BB*CC*DD];   // (phiK @ x^T)^T [b][c][m]
__device__ float g_KVT[BB*CC*DD];   // KV^T (no bias) [b][c][m]

__device__ __forceinline__ float fmap(float t) {
    return t > 0.f ? fmaf(PARAM, t, 1.f) : __expf(PARAM * t);
}
__device__ __forceinline__ uint32_t smaddr(const void* p) {
    return (uint32_t)__cvta_generic_to_shared(p);
}
#define CPA(d, s) asm volatile("cp.async.cg.shared.global [%0], [%1], 16;" \
        :: "r"(d), "l"(s) : "memory")
#define CPC()  asm volatile("cp.async.commit_group;" ::: "memory")
#define CPW0() asm volatile("cp.async.wait_group 0;" ::: "memory")
#define MMA8(d, a, b0, b1) \
    asm volatile("mma.sync.aligned.m16n8k8.row.col.f32.tf32.tf32.f32 " \
        "{%0,%1,%2,%3}, {%4,%5,%6,%7}, {%8,%9}, {%0,%1,%2,%3};" \
        : "+f"((d)[0]), "+f"((d)[1]), "+f"((d)[2]), "+f"((d)[3]) \
        : "r"((a)[0]), "r"((a)[1]), "r"((a)[2]), "r"((a)[3]), "r"(b0), "r"(b1))

// ---------------------------------------------------------------------------
__global__ void k_zero() {
    int i = blockIdx.x*blockDim.x + threadIdx.x;
    if (i < BB*CC*DD) { g_KXT[i] = 0.f; g_KVT[i] = 0.f; }
    if (i < BB*DD) g_Ksum[i] = 0.f;
}

// ---------------------------------------------------------------------------
// k_qk: [Wq;Wk](128x512) @ x_tile(512 x 128n). cp.async 2-stage, 2 blocks/SM.
// Epilogue: bias+fmap; Q->g_Q, K->g_Kt + Ksum atomics.
// ---------------------------------------------------------------------------
__global__ __launch_bounds__(256, 2) void k_qk(const float* __restrict__ x,
        const float* __restrict__ Wq, const float* __restrict__ bq,
        const float* __restrict__ Wk, const float* __restrict__ bk) {
    extern __shared__ float S[];   // 2 x (As 128*36 + Bs 32*136) = 2*8960
    const int tid = threadIdx.x, w = tid>>5, lane = tid&31;
    const int gr = lane>>2, qt = lane&3;
    const int b = blockIdx.y, n0 = blockIdx.x*128;
    const int M0 = (w>>1)*32, N0 = (w&1)*64;
    const float* xb = x + (size_t)b*CC*NN;

    auto issue = [&](int st, int kc) {
        float* As = S + st*8960;
        float* Bs = As + 4608;
        #pragma unroll
        for (int i = 0; i < 4; i++) {
            int id = tid + i*256, r = id>>3, c4 = id&7;
            const float* src = (r < 64 ? Wq + r*CC : Wk + (size_t)(r-64)*CC)
                               + kc + c4*4;
            CPA(smaddr(&As[r*36 + c4*4]), src);
        }
        #pragma unroll
        for (int i = 0; i < 4; i++) {
            int id = tid + i*256, r = id>>5, n4 = id&31;
            CPA(smaddr(&Bs[r*136 + n4*4]), xb + (size_t)(kc+r)*NN + n0 + n4*4);
        }
        CPC();
    };

    float acc[2][8][4];
    #pragma unroll
    for (int mt = 0; mt < 2; mt++)
        #pragma unroll
        for (int nt = 0; nt < 8; nt++)
            #pragma unroll
            for (int i = 0; i < 4; i++) acc[mt][nt][i] = 0.f;

    issue(0, 0);
    for (int ci = 0; ci < 16; ci++) {
        CPW0();
        __syncthreads();
        if (ci < 15) issue((ci+1)&1, (ci+1)*32);
        float* As = S + (ci&1)*8960;
        float* Bs = As + 4608;
        #pragma unroll
        for (int k0 = 0; k0 < 32; k0 += 8) {
            uint32_t af[2][4], bf[8][2];
            #pragma unroll
            for (int mt = 0; mt < 2; mt++) {
                int base = (M0 + 16*mt + gr)*36 + k0 + qt;
                af[mt][0] = __float_as_uint(As[base]);
                af[mt][1] = __float_as_uint(As[base + 8*36]);
                af[mt][2] = __float_as_uint(As[base + 4]);
                af[mt][3] = __float_as_uint(As[base + 8*36 + 4]);
            }
            #pragma unroll
            for (int nt = 0; nt < 8; nt++) {
                int bb = (k0 + qt)*136 + N0 + 8*nt + gr;
                bf[nt][0] = __float_as_uint(Bs[bb]);
                bf[nt][1] = __float_as_uint(Bs[bb + 4*136]);
            }
            #pragma unroll
            for (int mt = 0; mt < 2; mt++)
                #pragma unroll
                for (int nt = 0; nt < 8; nt++)
                    MMA8(acc[mt][nt], af[mt], bf[nt][0], bf[nt][1]);
        }
    }

    #pragma unroll
    for (int mt = 0; mt < 2; mt++)
        #pragma unroll
        for (int h = 0; h < 2; h++) {
            const int m = M0 + 16*mt + 8*h + gr;
            const float bias = m < 64 ? __ldg(bq + m) : __ldg(bk + m - 64);
            float vv[8][2], ks = 0.f;
            #pragma unroll
            for (int nt = 0; nt < 8; nt++) {
                vv[nt][0] = fmap(acc[mt][nt][2*h]   + bias);
                vv[nt][1] = fmap(acc[mt][nt][2*h+1] + bias);
                ks += vv[nt][0] + vv[nt][1];
            }
            if (m < 64) {
                float* dst = g_Q + ((size_t)b*DD + m)*NN + n0 + N0;
                #pragma unroll
                for (int nt = 0; nt < 8; nt++)
                    *(float2*)(dst + 8*nt + 2*qt) = make_float2(vv[nt][0], vv[nt][1]);
            } else {
                const int mm = m - 64;
                #pragma unroll
                for (int nt = 0; nt < 8; nt++) {
                    int n = n0 + N0 + 8*nt + 2*qt;
                    float* dk = g_Kt + ((size_t)b*NN + n)*DD + mm;
                    dk[0] = vv[nt][0]; dk[DD] = vv[nt][1];
                }
                ks += __shfl_xor_sync(0xffffffffu, ks, 1);
                ks += __shfl_xor_sync(0xffffffffu, ks, 2);
                if (qt == 0) atomicAdd(&g_Ksum[b*DD + mm], ks);
            }
        }
}

// ---------------------------------------------------------------------------
// k_kx: KXT[256c][64m] += x_tile @ phiK^T. cp.async 2-stage, 2 blocks/SM,
// warp tile 64c x 32m (mt=4), split-K=16, L2 atomics.
// ---------------------------------------------------------------------------
__global__ __launch_bounds__(256, 2) void k_kx(const float* __restrict__ x) {
    extern __shared__ float S[];   // 2 x (As 256*36=9216 + Bs 32*72=2304)
    const int tid = threadIdx.x, w = tid>>5, lane = tid&31;
    const int gr = lane>>2, qt = lane&3;
    const int c0 = blockIdx.x*256, b = blockIdx.z;
    const int nbase = blockIdx.y*(NN/16);
    const int CW = (w>>1)*64, N0 = (w&1)*32;

    auto issue = [&](int st, int kn) {
        float* As = S + st*11520;
        float* Bs = As + 9216;
        #pragma unroll
        for (int i = 0; i < 8; i++) {
            int id = tid + i*256, r = id>>3, n4 = id&7;
            CPA(smaddr(&As[r*36 + n4*4]),
                x + ((size_t)(b*CC + c0 + r))*NN + kn + n4*4);
        }
        #pragma unroll
        for (int i = 0; i < 2; i++) {
            int id = tid + i*256, r = id>>4, m4 = id&15;
            CPA(smaddr(&Bs[r*72 + m4*4]),
                g_Kt + ((size_t)b*NN + kn + r)*DD + m4*4);
        }
        CPC();
    };

    float acc[4][4][4];
    #pragma unroll
    for (int mt = 0; mt < 4; mt++)
        #pragma unroll
        for (int nt = 0; nt < 4; nt++)
            #pragma unroll
            for (int i = 0; i < 4; i++) acc[mt][nt][i] = 0.f;

    issue(0, nbase);
    for (int ci = 0; ci < 32; ci++) {
        CPW0();
        __syncthreads();
        if (ci < 31) issue((ci+1)&1, nbase + (ci+1)*32);
        float* As = S + (ci&1)*11520;
        float* Bs = As + 9216;
        #pragma unroll
        for (int k0 = 0; k0 < 32; k0 += 8) {
            uint32_t bf[4][2];
            #pragma unroll
            for (int nt = 0; nt < 4; nt++) {
                int bb = (k0 + qt)*72 + N0 + 8*nt + gr;
                bf[nt][0] = __float_as_uint(Bs[bb]);
                bf[nt][1] = __float_as_uint(Bs[bb + 4*72]);
            }
            #pragma unroll
            for (int mt = 0; mt < 4; mt++) {
                uint32_t af[4];
                int base = (CW + 16*mt + gr)*36 + k0 + qt;
                af[0] = __float_as_uint(As[base]);
                af[1] = __float_as_uint(As[base + 8*36]);
                af[2] = __float_as_uint(As[base + 4]);
                af[3] = __float_as_uint(As[base + 8*36 + 4]);
                #pragma unroll
                for (int nt = 0; nt < 4; nt++)
                    MMA8(acc[mt][nt], af, bf[nt][0], bf[nt][1]);
            }
        }
    }
    #pragma unroll
    for (int mt = 0; mt < 4; mt++)
        #pragma unroll
        for (int h = 0; h < 2; h++) {
            int c = c0 + CW + 16*mt + 8*h + gr;
            #pragma unroll
            for (int nt = 0; nt < 4; nt++) {
                int m = N0 + 8*nt + 2*qt;
                float* d = g_KXT + ((size_t)b*CC + c)*DD + m;
                atomicAdd(d,     acc[mt][nt][2*h]);
                atomicAdd(d + 1, acc[mt][nt][2*h+1]);
            }
        }
}

// ---------------------------------------------------------------------------
// k_kv (SIMT, split-K=4): KVT[c][m] += sum_{c'} Wv[c][c'] * KXT[c'][m]
// ---------------------------------------------------------------------------
__global__ __launch_bounds__(256) void k_kv(const float* __restrict__ Wv) {
    __shared__ float Ws[64*36];
    __shared__ float Xs[32*68];
    const int c0 = blockIdx.x*64, sp = blockIdx.y, b = blockIdx.z;
    const int tid = threadIdx.x, tx = tid&15, ty = tid>>4;

    float acc[4][4] = {};
    for (int kk = 0; kk < 4; kk++) {
        const int cp0 = sp*128 + kk*32;
        #pragma unroll
        for (int i = 0; i < 2; i++) {
            int id = tid + i*256, r = id>>3, q4 = id&7;
            *(float4*)&Ws[r*36 + q4*4] =
                *(const float4*)(Wv + (size_t)(c0 + r)*CC + cp0 + q4*4);
        }
        #pragma unroll
        for (int i = 0; i < 2; i++) {
            int id = tid + i*256, r = id>>4, m4 = id&15;
            *(float4*)&Xs[r*68 + m4*4] =
                *(const float4*)(g_KXT + ((size_t)(b*CC) + cp0 + r)*DD + m4*4);
        }
        __syncthreads();
        #pragma unroll
        for (int k = 0; k < 32; k++) {
            float a[4], bb[4];
            #pragma unroll
            for (int i = 0; i < 4; i++) a[i] = Ws[(ty*4+i)*36 + k];
            #pragma unroll
            for (int j = 0; j < 4; j++) bb[j] = Xs[k*68 + tx*4 + j];
            #pragma unroll
            for (int i = 0; i < 4; i++)
                #pragma unroll
                for (int j = 0; j < 4; j++)
                    acc[i][j] = fmaf(a[i], bb[j], acc[i][j]);
        }
        __syncthreads();
    }
    #pragma unroll
    for (int i = 0; i < 4; i++)
        #pragma unroll
        for (int j = 0; j < 4; j++)
            atomicAdd(&g_KVT[((size_t)b*CC + c0 + ty*4+i)*DD + tx*4 + j], acc[i][j]);
}

// ---------------------------------------------------------------------------
// k_out: one block owns a 128-n stripe. B=phiQ loaded once; A = raw KVT via
// 2-stage cp.async (bias hoisted: out += bv[c]*kq[n]). 2 blocks/SM.
// Warp tile 16c x 64n. 1024 blocks.
// ---------------------------------------------------------------------------
__global__ __launch_bounds__(256, 2) void k_out(const float* __restrict__ x,
        const float* __restrict__ bv, const float* __restrict__ gamma,
        float* __restrict__ out) {
    extern __shared__ float S[];   // As[2][64*68]=2*4352 then Bs[64*136]=8704
    float* Bs = S + 2*4352;
    __shared__ float rns[128], kqn[128], kss[64];
    const int tid = threadIdx.x, w = tid>>5, lane = tid&31;
    const int gr = lane>>2, qt = lane&3;
    const int n0 = blockIdx.x*128, b = blockIdx.y;
    const int M0 = (w>>1)*16, N0 = (w&1)*64;
    const float* kvb = g_KVT + (size_t)b*CC*DD;

    auto issueA = [&](int st, int c0) {
        float* As = S + st*4352;
        #pragma unroll
        for (int i = 0; i < 4; i++) {
            int id = tid + i*256, r = id>>4, m4 = id&15;
            CPA(smaddr(&As[r*68 + m4*4]), kvb + (size_t)(c0 + r)*DD + m4*4);
        }
        CPC();
    };

    issueA(0, 0);
    if (tid < 64) kss[tid] = g_Ksum[b*DD + tid];
    #pragma unroll
    for (int i = 0; i < 8; i++) {        // B = phiQ [m][128n], loaded once
        int id = tid + i*256, r = id>>5, n4 = id&31;
        *(float4*)&Bs[r*136 + n4*4] =
            *(const float4*)(g_Q + ((size_t)b*DD + r)*NN + n0 + n4*4);
    }
    __syncthreads();
    const float gm = gamma[0];
    if (tid < 128) {                     // den, qsum -> rns, kqn
        float d = 0.f, q = 0.f;
        #pragma unroll 16
        for (int m = 0; m < 64; m++) {
            float qv = Bs[m*136 + tid];
            d = fmaf(qv, kss[m] + EPS, d);
            q += qv;
        }
        rns[tid] = gm / d;
        kqn[tid] = d - EPS*q;            // sum_m Ksum[m]*Q[m][n]
    }

    for (int cc = 0; cc < 8; cc++) {
        const int c0 = cc*64;
        CPW0();
        __syncthreads();                 // As(cc) ready; rns/kqn visible
        if (cc < 7) issueA((cc+1)&1, c0 + 64);
        float* As = S + (cc&1)*4352;

        float acc[8][4];
        #pragma unroll
        for (int nt = 0; nt < 8; nt++)
            #pragma unroll
            for (int i = 0; i < 4; i++) acc[nt][i] = 0.f;
        #pragma unroll
        for (int k0 = 0; k0 < 64; k0 += 8) {
            uint32_t af[4], bf[8][2];
            int base = (M0 + gr)*68 + k0 + qt;
            af[0] = __float_as_uint(As[base]);
            af[1] = __float_as_uint(As[base + 8*68]);
            af[2] = __float_as_uint(As[base + 4]);
            af[3] = __float_as_uint(As[base + 8*68 + 4]);
            #pragma unroll
            for (int nt = 0; nt < 8; nt++) {
                int bb = (k0 + qt)*136 + N0 + 8*nt + gr;
                bf[nt][0] = __float_as_uint(Bs[bb]);
                bf[nt][1] = __float_as_uint(Bs[bb + 4*136]);
            }
            #pragma unroll
            for (int nt = 0; nt < 8; nt++)
                MMA8(acc[nt], af, bf[nt][0], bf[nt][1]);
        }
        #pragma unroll
        for (int h = 0; h < 2; h++) {
            const int c = c0 + M0 + 8*h + gr;
            const float bvc = __ldg(bv + c);
            #pragma unroll
            for (int nt = 0; nt < 8; nt++) {
                const int nl = N0 + 8*nt + 2*qt;
                const size_t bi = ((size_t)b*CC + c)*NN + n0 + nl;
                float2 xv = *(const float2*)(x + bi);
                float t0 = fmaf(bvc, kqn[nl],   acc[nt][2*h]);
                float t1 = fmaf(bvc, kqn[nl+1], acc[nt][2*h+1]);
                float2 o;
                o.x = fmaf(t0, rns[nl],   xv.x);
                o.y = fmaf(t1, rns[nl+1], xv.y);
                *(float2*)(out + bi) = o;
            }
        }
    }
}

// ---------------------------------------------------------------------------
extern "C" void kernel_launch(void* const* d_in, const int* in_sizes, int n_in,
                              void* d_out, int out_size) {
    const float* x     = (const float*)d_in[0];
    const float* Wq    = (const float*)d_in[1];
    const float* bq    = (const float*)d_in[2];
    const float* Wk    = (const float*)d_in[3];
    const float* bk    = (const float*)d_in[4];
    const float* Wv    = (const float*)d_in[5];
    const float* bv    = (const float*)d_in[6];
    const float* gamma = (const float*)d_in[7];
    float* out = (float*)d_out;

    cudaFuncSetAttribute(k_qk,  cudaFuncAttributeMaxDynamicSharedMemorySize, 71680);
    cudaFuncSetAttribute(k_kx,  cudaFuncAttributeMaxDynamicSharedMemorySize, 92160);
    cudaFuncSetAttribute(k_out, cudaFuncAttributeMaxDynamicSharedMemorySize, 69632);

    k_zero<<<512, 512>>>();
    k_qk  <<<dim3(NN/128, BB), 256, 71680>>>(x, Wq, bq, Wk, bk);
    k_kx  <<<dim3(CC/256, 16, BB), 256, 92160>>>(x);
    k_kv  <<<dim3(CC/64, 4, BB), 256>>>(Wv);
    k_out <<<dim3(NN/128, BB), 256, 69632>>>(x, bv, gamma, out);
}